// round 5
// baseline (speedup 1.0000x reference)
#include <cuda_runtime.h>
#include <cuda_bf16.h>
#include <cstdint>

#define VOCAB   50257
#define VPAD    50432        /* 197 * 256 */
#define NTILES  197
#define NEMBD   768
#define NROWS   8192
#define SEQLEN  1024
#define NSPLIT  9
#define NCHUNK  6            /* 768 / 128 */
#define BN      256

#define A_CHUNK 16384        /* 128 rows x 128 fp8 */
#define B_CHUNK 32768        /* 256 rows x 128 fp8 */
#define SMEM_A_OFF 0
#define SMEM_B_OFF (NCHUNK * A_CHUNK)              /* 98304 */
#define SMEM_BYTES (SMEM_B_OFF + 4 * B_CHUNK)      /* 229376 */

#define QSCALE   64.0f
#define QDESCALE (1.0f / 4096.0f)   /* 1/(64*64) */

// ---------------- device scratch ----------------
__device__ __align__(256) uint8_t g_X8[(size_t)NROWS * NEMBD];   // e4m3(gelu(wte+wpe) * 64)
__device__ __align__(256) uint8_t g_W8[(size_t)VPAD * NEMBD];    // e4m3(W * 64), zero-padded
__device__ float g_pmax[NSPLIT][2][NROWS];
__device__ float g_psum[NSPLIT][2][NROWS];
__device__ float g_ll[NROWS];
__device__ float g_row[NROWS];

// ---------------- helpers ----------------
__device__ __forceinline__ uint32_t smem_u32(const void* p) {
    uint32_t a;
    asm("{ .reg .u64 t; cvta.to.shared.u64 t, %1; cvt.u32.u64 %0, t; }" : "=r"(a) : "l"(p));
    return a;
}
__device__ __forceinline__ void cp_async16(uint32_t dst, const void* src) {
    asm volatile("cp.async.cg.shared.global [%0], [%1], 16;" :: "r"(dst), "l"(src));
}
__device__ __forceinline__ void cp_commit() {
    asm volatile("cp.async.commit_group;" ::: "memory");
}
template <int N>
__device__ __forceinline__ void cp_wait() {
    asm volatile("cp.async.wait_group %0;" :: "n"(N) : "memory");
}
__device__ __forceinline__ void ldsm_x4(uint32_t (&r)[4], uint32_t addr) {
    asm volatile("ldmatrix.sync.aligned.m8n8.x4.shared.b16 {%0,%1,%2,%3}, [%4];"
                 : "=r"(r[0]), "=r"(r[1]), "=r"(r[2]), "=r"(r[3]) : "r"(addr));
}
// fp8 e4m3 MMA, fp32 accum (sm_89+ PTX, not arch-'a' gated)
__device__ __forceinline__ void mma16832(float* c, const uint32_t* a, uint32_t b0, uint32_t b1) {
    asm volatile(
        "mma.sync.aligned.m16n8k32.row.col.f32.e4m3.e4m3.f32 "
        "{%0,%1,%2,%3}, {%4,%5,%6,%7}, {%8,%9}, {%0,%1,%2,%3};"
        : "+f"(c[0]), "+f"(c[1]), "+f"(c[2]), "+f"(c[3])
        : "r"(a[0]), "r"(a[1]), "r"(a[2]), "r"(a[3]), "r"(b0), "r"(b1));
}
__device__ __forceinline__ uint32_t swz(uint32_t bo) { return bo ^ ((bo >> 3) & 0x70u); }
// pack 2 floats -> 2 e4m3 (lo byte = first arg of pair ordering below)
__device__ __forceinline__ uint16_t pack_e4m3x2(float lo, float hi) {
    uint16_t r;
    asm("cvt.rn.satfinite.e4m3x2.f32 %0, %1, %2;" : "=h"(r) : "f"(hi), "f"(lo));
    return r;
}
// unpack 2 e4m3 -> half2 (as u32)
__device__ __forceinline__ uint32_t unpack_e4m3x2(uint16_t v) {
    uint32_t r;
    asm("cvt.rn.f16x2.e4m3x2 %0, %1;" : "=r"(r) : "h"(v));
    return r;
}

// ---------------- kernel 1: x = e4m3(gelu(wte[tok] + wpe[pos]) * 64) ----------------
__global__ void prep_x_kernel(const int* __restrict__ data, const float* __restrict__ wte,
                              const float* __restrict__ wpe) {
    int idx = blockIdx.x * blockDim.x + threadIdx.x;   // over NROWS * 192
    if (idx >= NROWS * (NEMBD / 4)) return;
    int row = idx / (NEMBD / 4);
    int c4  = idx % (NEMBD / 4);
    int tok = data[row];
    int pos = row & (SEQLEN - 1);
    float4 a = *reinterpret_cast<const float4*>(wte + (size_t)tok * NEMBD + c4 * 4);
    float4 p = *reinterpret_cast<const float4*>(wpe + (size_t)pos * NEMBD + c4 * 4);
    const float K0 = 0.7978845608028654f, K1 = 0.044715f;
    float v[4] = {a.x + p.x, a.y + p.y, a.z + p.z, a.w + p.w};
    float g[4];
#pragma unroll
    for (int i = 0; i < 4; i++) {
        float x = v[i];
        g[i] = 0.5f * x * (1.0f + tanhf(K0 * (x + K1 * x * x * x))) * QSCALE;
    }
    uint32_t packed = (uint32_t)pack_e4m3x2(g[0], g[1])
                    | ((uint32_t)pack_e4m3x2(g[2], g[3]) << 16);
    *reinterpret_cast<uint32_t*>(&g_X8[(size_t)row * NEMBD + c4 * 4]) = packed;
}

// ---------------- kernel 2: W -> e4m3(W * 64), zero-padded rows ----------------
__global__ void conv_w_kernel(const float* __restrict__ W) {
    int idx = blockIdx.x * blockDim.x + threadIdx.x;   // over VPAD * 192
    if (idx >= VPAD * (NEMBD / 4)) return;
    int v  = idx / (NEMBD / 4);
    int c4 = idx % (NEMBD / 4);
    uint32_t packed = 0;
    if (v < VOCAB) {
        float4 w = *reinterpret_cast<const float4*>(W + (size_t)v * NEMBD + c4 * 4);
        packed = (uint32_t)pack_e4m3x2(w.x * QSCALE, w.y * QSCALE)
               | ((uint32_t)pack_e4m3x2(w.z * QSCALE, w.w * QSCALE) << 16);
    }
    *reinterpret_cast<uint32_t*>(&g_W8[(size_t)v * NEMBD + c4 * 4]) = packed;
}

// ---------------- kernel 3: fused FP8 GEMM + online logsumexp ----------------
// 256 threads = 8 warps (4M x 2N); warp tile 32x128; CTA tile 128x256.
// A (128x768 fp8) resident; B streamed continuously, 4 buffers, wait_group<2>,
// one __syncthreads per chunk; prefetch g+3 issued mid-chunk (into buffer last
// read at g-1, protected by the barrier at top of chunk g).
__global__ void __launch_bounds__(256, 1)
gemm_lse_kernel() {
    extern __shared__ char smem[];
    const uint32_t smem_base = smem_u32(smem);
    const int tid  = threadIdx.x;
    const int lane = tid & 31;
    const int wid  = tid >> 5;
    const int wm   = wid >> 1;
    const int wn   = wid & 1;
    const int s    = blockIdx.x;
    const int m0   = blockIdx.y * 128;

    const int rb  = tid >> 3;            // 0..31
    const int seg = tid & 7;             // 0..7
    uint32_t off8[8];
#pragma unroll
    for (int j = 0; j < 8; j++)
        off8[j] = swz((uint32_t)(rb + j * 32) * 128u + (uint32_t)seg * 16u);

    // ---- resident A: 6 chunks of 128x128 fp8 (one group) ----
#pragma unroll 1
    for (int kk = 0; kk < NCHUNK; kk++) {
        uint32_t abase = smem_base + SMEM_A_OFF + kk * A_CHUNK;
        const uint8_t* src = &g_X8[(size_t)(m0 + rb) * NEMBD + kk * 128 + seg * 16];
#pragma unroll
        for (int j = 0; j < 4; j++)
            cp_async16(abase + off8[j], src + (size_t)j * 32 * NEMBD);
    }
    cp_commit();

    // vocab tile range: 197 = 8*22 + 21
    const int t0   = s * 22;
    const int tcnt = (s == 8) ? 21 : 22;
    const int NC   = tcnt * NCHUNK;

    // ---- B prologue: chunks 0,1,2 (one group each) ----
#pragma unroll
    for (int pre = 0; pre < 3; pre++) {
        uint32_t bbase = smem_base + SMEM_B_OFF + pre * B_CHUNK;
        const uint8_t* src = &g_W8[(size_t)(t0 * BN + rb) * NEMBD + pre * 128 + seg * 16];
#pragma unroll
        for (int j = 0; j < 8; j++)
            cp_async16(bbase + off8[j], src + (size_t)j * 32 * NEMBD);
        cp_commit();
    }

    // ---- ldmatrix lane constants (b16 view: 64 b16-cols per 128-fp8 row) ----
    const int quad = lane >> 3;
    const int lrow = lane & 7;
    const int a_row = wm * 32 + (quad & 1) * 8 + lrow;     // + mi*16
    const int a_k16 = (quad >> 1) * 16;                    // byte offset of k16-half
    const int b_row = wn * 128 + (quad >> 1) * 8 + lrow;   // + nt*16
    const int b_k16 = (quad & 1) * 16;

    float m_run[4], s_run[4];
#pragma unroll
    for (int i = 0; i < 4; i++) { m_run[i] = -3.0e38f; s_run[i] = 0.0f; }

    float c[2][16][4];
#pragma unroll
    for (int mi = 0; mi < 2; mi++)
#pragma unroll
        for (int nj = 0; nj < 16; nj++)
#pragma unroll
            for (int e = 0; e < 4; e++) c[mi][nj][e] = 0.0f;

    int v0 = t0 * BN;       // current tile vocab base
    int kk = 0;             // chunk within tile
    int vp = t0 * BN;       // prefetch vocab base (global chunk g+3)
    int kp = 3;             // prefetch chunk-in-tile

#pragma unroll 1
    for (int g = 0; g < NC; g++) {
        cp_wait<2>();
        __syncthreads();

        const uint32_t Ab = smem_base + SMEM_A_OFF + kk * A_CHUNK;
        const uint32_t Bb = smem_base + SMEM_B_OFF + (g & 3) * B_CHUNK;

        // ---- ks = 0: LDSMs, then prefetch, then MMAs ----
        uint32_t a0[2][4];
#pragma unroll
        for (int mi = 0; mi < 2; mi++)
            ldsm_x4(a0[mi], Ab + swz((uint32_t)(a_row + mi * 16) * 128u + a_k16));
        uint32_t bfr[8][4];
#pragma unroll
        for (int nt = 0; nt < 8; nt++)
            ldsm_x4(bfr[nt], Bb + swz((uint32_t)(b_row + nt * 16) * 128u + b_k16));

        if (g + 3 < NC) {
            uint32_t bbase = smem_base + SMEM_B_OFF + ((g + 3) & 3) * B_CHUNK;
            const uint8_t* src = &g_W8[(size_t)(vp + rb) * NEMBD + kp * 128 + seg * 16];
#pragma unroll
            for (int j = 0; j < 8; j++)
                cp_async16(bbase + off8[j], src + (size_t)j * 32 * NEMBD);
        }
        cp_commit();
        kp++;
        if (kp == NCHUNK) { kp = 0; vp += BN; }

#pragma unroll
        for (int nt = 0; nt < 8; nt++)
#pragma unroll
            for (int mi = 0; mi < 2; mi++) {
                mma16832(c[mi][nt * 2 + 0], a0[mi], bfr[nt][0], bfr[nt][1]);
                mma16832(c[mi][nt * 2 + 1], a0[mi], bfr[nt][2], bfr[nt][3]);
            }

        // ---- ks = 1..3 ----
#pragma unroll
        for (int ks = 1; ks < 4; ks++) {
            const uint32_t kb = (uint32_t)ks * 32u;
            uint32_t a[2][4];
#pragma unroll
            for (int mi = 0; mi < 2; mi++)
                ldsm_x4(a[mi], Ab + swz((uint32_t)(a_row + mi * 16) * 128u + kb + a_k16));
#pragma unroll
            for (int nt = 0; nt < 8; nt++) {
                uint32_t b[4];
                ldsm_x4(b, Bb + swz((uint32_t)(b_row + nt * 16) * 128u + kb + b_k16));
#pragma unroll
                for (int mi = 0; mi < 2; mi++) {
                    mma16832(c[mi][nt * 2 + 0], a[mi], b[0], b[1]);
                    mma16832(c[mi][nt * 2 + 1], a[mi], b[2], b[3]);
                }
            }
        }

        kk++;
        if (kk == NCHUNK) {
            // ---- tile epilogue (registers only; overlaps in-flight prefetch) ----
            kk = 0;
            // descale to true logit space
#pragma unroll
            for (int mi = 0; mi < 2; mi++)
#pragma unroll
                for (int nj = 0; nj < 16; nj++)
#pragma unroll
                    for (int e = 0; e < 4; e++) c[mi][nj][e] *= QDESCALE;

            const bool edge = (v0 + BN > VOCAB);
            const int colb = v0 + wn * 128 + 2 * (lane & 3);
#pragma unroll
            for (int sl = 0; sl < 4; sl++) {
                const int mi = sl >> 1, h = sl & 1;
                float tm = -3.0e38f;
                if (!edge) {
#pragma unroll
                    for (int nj = 0; nj < 16; nj++) {
                        tm = fmaxf(tm, c[mi][nj][h * 2 + 0]);
                        tm = fmaxf(tm, c[mi][nj][h * 2 + 1]);
                    }
                } else {
#pragma unroll
                    for (int nj = 0; nj < 16; nj++)
#pragma unroll
                        for (int e = 0; e < 2; e++) {
                            float v = c[mi][nj][h * 2 + e];
                            if (colb + nj * 8 + e >= VOCAB) v = -3.0e38f;
                            tm = fmaxf(tm, v);
                        }
                }
                tm = fmaxf(tm, __shfl_xor_sync(0xFFFFFFFFu, tm, 1));
                tm = fmaxf(tm, __shfl_xor_sync(0xFFFFFFFFu, tm, 2));
                float nm = fmaxf(m_run[sl], tm);
                float p = 0.0f;
                if (!edge) {
#pragma unroll
                    for (int nj = 0; nj < 16; nj++) {
                        p += __expf(c[mi][nj][h * 2 + 0] - nm);
                        p += __expf(c[mi][nj][h * 2 + 1] - nm);
                    }
                } else {
#pragma unroll
                    for (int nj = 0; nj < 16; nj++)
#pragma unroll
                        for (int e = 0; e < 2; e++) {
                            float v = c[mi][nj][h * 2 + e];
                            if (colb + nj * 8 + e >= VOCAB) v = -3.0e38f;
                            p += __expf(v - nm);
                        }
                }
                p += __shfl_xor_sync(0xFFFFFFFFu, p, 1);
                p += __shfl_xor_sync(0xFFFFFFFFu, p, 2);
                s_run[sl] = s_run[sl] * __expf(m_run[sl] - nm) + p;
                m_run[sl] = nm;
            }
            v0 += BN;
#pragma unroll
            for (int mi = 0; mi < 2; mi++)
#pragma unroll
                for (int nj = 0; nj < 16; nj++)
#pragma unroll
                    for (int e = 0; e < 4; e++) c[mi][nj][e] = 0.0f;
        }
    }

    // ---- store per-row partials keyed by (s, wn) ----
    if ((lane & 3) == 0) {
#pragma unroll
        for (int sl = 0; sl < 4; sl++) {
            const int mi = sl >> 1, h = sl & 1;
            int row = m0 + wm * 32 + mi * 16 + h * 8 + (lane >> 2);
            g_pmax[s][wn][row] = m_run[sl];
            g_psum[s][wn][row] = s_run[sl];
        }
    }
}

// ---------------- kernel 4: label logits from the SAME fp8 operands ----------------
__global__ void label_logit_kernel(const int* __restrict__ label) {
    int wid = threadIdx.x >> 5, lid = threadIdx.x & 31;
    int row = blockIdx.x * 8 + wid;
    int lab = label[row];
    const uint32_t* xr = reinterpret_cast<const uint32_t*>(&g_X8[(size_t)row * NEMBD]);
    const uint32_t* wr = reinterpret_cast<const uint32_t*>(&g_W8[(size_t)lab * NEMBD]);
    float acc = 0.f;
#pragma unroll
    for (int it = 0; it < 6; it++) {
        uint32_t xv = xr[it * 32 + lid];
        uint32_t wv = wr[it * 32 + lid];
        uint32_t x01 = unpack_e4m3x2((uint16_t)(xv & 0xFFFFu));
        uint32_t x23 = unpack_e4m3x2((uint16_t)(xv >> 16));
        uint32_t w01 = unpack_e4m3x2((uint16_t)(wv & 0xFFFFu));
        uint32_t w23 = unpack_e4m3x2((uint16_t)(wv >> 16));
        __half2 xh0 = *reinterpret_cast<__half2*>(&x01);
        __half2 xh1 = *reinterpret_cast<__half2*>(&x23);
        __half2 wh0 = *reinterpret_cast<__half2*>(&w01);
        __half2 wh1 = *reinterpret_cast<__half2*>(&w23);
        acc += __low2float(xh0) * __low2float(wh0) + __high2float(xh0) * __high2float(wh0)
             + __low2float(xh1) * __low2float(wh1) + __high2float(xh1) * __high2float(wh1);
    }
#pragma unroll
    for (int o = 16; o; o >>= 1) acc += __shfl_xor_sync(0xFFFFFFFFu, acc, o);
    if (lid == 0) g_ll[row] = acc * QDESCALE;
}

// ---------------- kernel 5a: per-row NLL ----------------
__global__ void rownll_kernel() {
    int r = blockIdx.x * 256 + threadIdx.x;
    float m = g_pmax[0][0][r];
#pragma unroll
    for (int s = 0; s < NSPLIT; s++) {
        m = fmaxf(m, g_pmax[s][0][r]);
        m = fmaxf(m, g_pmax[s][1][r]);
    }
    float S = 0.f;
#pragma unroll
    for (int s = 0; s < NSPLIT; s++) {
        S += g_psum[s][0][r] * __expf(g_pmax[s][0][r] - m);
        S += g_psum[s][1][r] * __expf(g_pmax[s][1][r] - m);
    }
    g_row[r] = (m + logf(S)) - g_ll[r];
}

// ---------------- kernel 5b: deterministic mean ----------------
__global__ void reduce_kernel(float* __restrict__ out) {
    __shared__ float red[256];
    int t = threadIdx.x;
    float local = 0.f;
#pragma unroll
    for (int i = 0; i < NROWS / 256; i++) local += g_row[t + i * 256];
    red[t] = local;
    __syncthreads();
    for (int off = 128; off; off >>= 1) {
        if (t < off) red[t] += red[t + off];
        __syncthreads();
    }
    if (t == 0) out[0] = red[0] * (1.0f / (float)NROWS);
}

// ---------------- launch ----------------
extern "C" void kernel_launch(void* const* d_in, const int* in_sizes, int n_in,
                              void* d_out, int out_size) {
    const int*   data  = (const int*)d_in[0];
    const int*   label = (const int*)d_in[1];
    const float* wte   = (const float*)d_in[2];
    const float* wpe   = (const float*)d_in[3];
    const float* W     = (const float*)d_in[4];
    float* out = (float*)d_out;

    cudaFuncSetAttribute(gemm_lse_kernel, cudaFuncAttributeMaxDynamicSharedMemorySize, SMEM_BYTES);

    prep_x_kernel<<<(NROWS * (NEMBD / 4)) / 256, 256>>>(data, wte, wpe);
    conv_w_kernel<<<(VPAD * (NEMBD / 4)) / 256, 256>>>(W);
    gemm_lse_kernel<<<dim3(NSPLIT, NROWS / 128), 256, SMEM_BYTES>>>();
    label_logit_kernel<<<NROWS / 8, 256>>>(label);
    rownll_kernel<<<NROWS / 256, 256>>>();
    reduce_kernel<<<1, 256>>>(out);
}

// round 6
// speedup vs baseline: 1.0764x; 1.0764x over previous
#include <cuda_runtime.h>
#include <cuda_fp16.h>
#include <cstdint>

#define VOCAB   50257
#define VPAD    50304        /* 393 * 128 */
#define NEMBD   768
#define NROWS   8192
#define SEQLEN  1024
#define NSPLIT  9
#define NCHUNK  12           /* 768 / 64 */

#define SMEM_A_OFF 0
#define SMEM_B_OFF (NCHUNK * 16384)             /* 196608 */
#define SMEM_BYTES (SMEM_B_OFF + 2 * 16384)     /* 229376 */

// ---------------- device scratch ----------------
__device__ __align__(256) __half g_X[(size_t)NROWS * NEMBD];   // fp16(gelu(wte+wpe))
__device__ __align__(256) __half g_W[(size_t)VPAD * NEMBD];    // fp16(W), zero-padded
__device__ float g_pmax[NSPLIT][2][NROWS];
__device__ float g_psum[NSPLIT][2][NROWS];
__device__ float g_ll[NROWS];
__device__ float g_row[NROWS];

// ---------------- helpers ----------------
__device__ __forceinline__ uint32_t smem_u32(const void* p) {
    uint32_t a;
    asm("{ .reg .u64 t; cvta.to.shared.u64 t, %1; cvt.u32.u64 %0, t; }" : "=r"(a) : "l"(p));
    return a;
}
__device__ __forceinline__ void cp_async16(uint32_t dst, const void* src) {
    asm volatile("cp.async.cg.shared.global [%0], [%1], 16;" :: "r"(dst), "l"(src));
}
__device__ __forceinline__ void cp_commit() {
    asm volatile("cp.async.commit_group;" ::: "memory");
}
template <int N>
__device__ __forceinline__ void cp_wait() {
    asm volatile("cp.async.wait_group %0;" :: "n"(N) : "memory");
}
__device__ __forceinline__ void ldsm_x4(uint32_t (&r)[4], uint32_t addr) {
    asm volatile("ldmatrix.sync.aligned.m8n8.x4.shared.b16 {%0,%1,%2,%3}, [%4];"
                 : "=r"(r[0]), "=r"(r[1]), "=r"(r[2]), "=r"(r[3]) : "r"(addr));
}
// fp16 in, fp16 accumulate (full-rate HMMA path); D/C are 2x f16x2 regs
__device__ __forceinline__ void mma16816_f16(uint32_t* c, const uint32_t* a, const uint32_t* b) {
    asm volatile(
        "mma.sync.aligned.m16n8k16.row.col.f16.f16.f16.f16 "
        "{%0,%1}, {%2,%3,%4,%5}, {%6,%7}, {%0,%1};"
        : "+r"(c[0]), "+r"(c[1])
        : "r"(a[0]), "r"(a[1]), "r"(a[2]), "r"(a[3]), "r"(b[0]), "r"(b[1]));
}
__device__ __forceinline__ uint32_t swz(uint32_t bo) { return bo ^ ((bo >> 3) & 0x70u); }

// ---------------- kernel 1: x = fp16(gelu(wte[tok] + wpe[pos])) ----------------
__global__ void prep_x_kernel(const int* __restrict__ data, const float* __restrict__ wte,
                              const float* __restrict__ wpe) {
    int idx = blockIdx.x * blockDim.x + threadIdx.x;
    if (idx >= NROWS * (NEMBD / 4)) return;
    int row = idx / (NEMBD / 4);
    int c4  = idx % (NEMBD / 4);
    int tok = data[row];
    int pos = row & (SEQLEN - 1);
    float4 a = *reinterpret_cast<const float4*>(wte + (size_t)tok * NEMBD + c4 * 4);
    float4 p = *reinterpret_cast<const float4*>(wpe + (size_t)pos * NEMBD + c4 * 4);
    const float K0 = 0.7978845608028654f, K1 = 0.044715f;
    float v[4] = {a.x + p.x, a.y + p.y, a.z + p.z, a.w + p.w};
    float g[4];
#pragma unroll
    for (int i = 0; i < 4; i++) {
        float x = v[i];
        g[i] = 0.5f * x * (1.0f + tanhf(K0 * (x + K1 * x * x * x)));
    }
    __half2* dst = reinterpret_cast<__half2*>(&g_X[(size_t)row * NEMBD + c4 * 4]);
    dst[0] = __floats2half2_rn(g[0], g[1]);
    dst[1] = __floats2half2_rn(g[2], g[3]);
}

// ---------------- kernel 2: W fp32 -> fp16 (zero-padded rows) ----------------
__global__ void conv_w_kernel(const float* __restrict__ W) {
    int idx = blockIdx.x * blockDim.x + threadIdx.x;
    if (idx >= VPAD * (NEMBD / 4)) return;
    int v  = idx / (NEMBD / 4);
    int c4 = idx % (NEMBD / 4);
    __half2 r0, r1;
    if (v < VOCAB) {
        float4 w = *reinterpret_cast<const float4*>(W + (size_t)v * NEMBD + c4 * 4);
        r0 = __floats2half2_rn(w.x, w.y);
        r1 = __floats2half2_rn(w.z, w.w);
    } else {
        r0 = __floats2half2_rn(0.f, 0.f);
        r1 = r0;
    }
    __half2* dst = reinterpret_cast<__half2*>(&g_W[(size_t)v * NEMBD + c4 * 4]);
    dst[0] = r0;
    dst[1] = r1;
}

// ---------------- kernel 3: fused GEMM (fp16 mma, fp16 accum) + online logsumexp ----------------
// 256 threads = 8 warps (4M x 2N); warp tile 32x64; CTA tile 128x128.
// A (128x768 fp16) resident; B streamed continuously, 2 buffers, one barrier/chunk.
__global__ void __launch_bounds__(256, 1)
gemm_lse_kernel() {
    extern __shared__ char smem[];
    const uint32_t smem_base = smem_u32(smem);
    const int tid  = threadIdx.x;
    const int lane = tid & 31;
    const int wid  = tid >> 5;
    const int wm   = wid >> 1;
    const int wn   = wid & 1;
    const int s    = blockIdx.x;
    const int m0   = blockIdx.y * 128;

    const int rb  = tid >> 3;           // 0..31
    const int seg = tid & 7;            // 0..7
    const uint32_t cpo  = swz((uint32_t)rb * 128u + (uint32_t)seg * 16u);
    const uint32_t cpo1 = swz((uint32_t)(rb + 32) * 128u + (uint32_t)seg * 16u);
    const uint32_t cpo2 = swz((uint32_t)(rb + 64) * 128u + (uint32_t)seg * 16u);
    const uint32_t cpo3 = swz((uint32_t)(rb + 96) * 128u + (uint32_t)seg * 16u);

    // ---- resident A: 12 chunks of 128x64 fp16 (one group) ----
#pragma unroll 1
    for (int kk = 0; kk < NCHUNK; kk++) {
        uint32_t abase = smem_base + SMEM_A_OFF + kk * 16384;
        const __half* src = &g_X[(size_t)(m0 + rb) * NEMBD + kk * 64 + seg * 8];
        cp_async16(abase + cpo,  src);
        cp_async16(abase + cpo1, src + 32 * NEMBD);
        cp_async16(abase + cpo2, src + 64 * NEMBD);
        cp_async16(abase + cpo3, src + 96 * NEMBD);
    }
    cp_commit();

    // vocab tile range: 393 = 6*44 + 3*43
    const int t0   = s * 43 + (s < 6 ? s : 6);
    const int tcnt = 43 + (s < 6 ? 1 : 0);
    const int NC   = tcnt * NCHUNK;

    // ---- B chunk 0 into buf0 ----
    {
        uint32_t bbase = smem_base + SMEM_B_OFF;
        const __half* src = &g_W[(size_t)(t0 * 128 + rb) * NEMBD + seg * 8];
        cp_async16(bbase + cpo,  src);
        cp_async16(bbase + cpo1, src + 32 * NEMBD);
        cp_async16(bbase + cpo2, src + 64 * NEMBD);
        cp_async16(bbase + cpo3, src + 96 * NEMBD);
    }
    cp_commit();

    // ---- ldmatrix lane constants ----
    const int quad = lane >> 3;
    const int lrow = lane & 7;
    const int a_row = wm * 32 + (quad & 1) * 8 + lrow;
    const int a_c8  = (quad >> 1);
    const int b_row = wn * 64 + (quad >> 1) * 8 + lrow;
    const int b_c8  = (quad & 1);

    float m_run[4], s_run[4];
#pragma unroll
    for (int i = 0; i < 4; i++) { m_run[i] = -3.0e38f; s_run[i] = 0.0f; }

    // fp16 accumulators: c[mi][nj][h]: h=0 -> rows r (2 cols packed), h=1 -> rows r+8
    uint32_t c[2][8][2];
#pragma unroll
    for (int mi = 0; mi < 2; mi++)
#pragma unroll
        for (int nj = 0; nj < 8; nj++) { c[mi][nj][0] = 0u; c[mi][nj][1] = 0u; }

    int v0 = t0 * 128;
    int kk = 0;
    int vp = t0 * 128;
    int kp = 1;

#pragma unroll 1
    for (int g = 0; g < NC; g++) {
        cp_wait<0>();
        __syncthreads();

        const uint32_t Ab = smem_base + SMEM_A_OFF + kk * 16384;
        const uint32_t Bb = smem_base + SMEM_B_OFF + (g & 1) * 16384;

        // ks = 0 LDSMs, then prefetch, then MMAs
        uint32_t a0[2][4], b0[4][4];
#pragma unroll
        for (int mi = 0; mi < 2; mi++) {
            uint32_t bo = (uint32_t)(a_row + mi * 16) * 128u + (uint32_t)(a_c8 * 8) * 2u;
            ldsm_x4(a0[mi], Ab + swz(bo));
        }
#pragma unroll
        for (int p = 0; p < 4; p++) {
            uint32_t bo = (uint32_t)(b_row + p * 16) * 128u + (uint32_t)(b_c8 * 8) * 2u;
            ldsm_x4(b0[p], Bb + swz(bo));
        }

        if (g + 1 < NC) {
            uint32_t bbase = smem_base + SMEM_B_OFF + ((g + 1) & 1) * 16384;
            const __half* src = &g_W[(size_t)(vp + rb) * NEMBD + kp * 64 + seg * 8];
            cp_async16(bbase + cpo,  src);
            cp_async16(bbase + cpo1, src + 32 * NEMBD);
            cp_async16(bbase + cpo2, src + 64 * NEMBD);
            cp_async16(bbase + cpo3, src + 96 * NEMBD);
        }
        cp_commit();
        kp++;
        if (kp == NCHUNK) { kp = 0; vp += 128; }

#pragma unroll
        for (int mi = 0; mi < 2; mi++)
#pragma unroll
            for (int p = 0; p < 4; p++) {
                mma16816_f16(c[mi][p * 2 + 0], a0[mi], &b0[p][0]);
                mma16816_f16(c[mi][p * 2 + 1], a0[mi], &b0[p][2]);
            }

#pragma unroll
        for (int ks = 1; ks < 4; ks++) {
            const int kc = ks * 16;
            uint32_t a[2][4], b[4][4];
#pragma unroll
            for (int mi = 0; mi < 2; mi++) {
                uint32_t bo = (uint32_t)(a_row + mi * 16) * 128u
                            + (uint32_t)(kc + a_c8 * 8) * 2u;
                ldsm_x4(a[mi], Ab + swz(bo));
            }
#pragma unroll
            for (int p = 0; p < 4; p++) {
                uint32_t bo = (uint32_t)(b_row + p * 16) * 128u
                            + (uint32_t)(kc + b_c8 * 8) * 2u;
                ldsm_x4(b[p], Bb + swz(bo));
            }
#pragma unroll
            for (int mi = 0; mi < 2; mi++)
#pragma unroll
                for (int p = 0; p < 4; p++) {
                    mma16816_f16(c[mi][p * 2 + 0], a[mi], &b[p][0]);
                    mma16816_f16(c[mi][p * 2 + 1], a[mi], &b[p][2]);
                }
        }

        kk++;
        if (kk == NCHUNK) {
            // ---- tile epilogue (unpack fp16 accums; overlaps in-flight prefetch) ----
            kk = 0;
            const bool edge = (v0 + 128 > VOCAB);
            const int colb = v0 + wn * 64 + 2 * (lane & 3);
#pragma unroll
            for (int sl = 0; sl < 4; sl++) {
                const int mi = sl >> 1, h = sl & 1;
                float vv[8][2];
#pragma unroll
                for (int nj = 0; nj < 8; nj++) {
                    float2 f = __half22float2(*reinterpret_cast<__half2*>(&c[mi][nj][h]));
                    vv[nj][0] = f.x; vv[nj][1] = f.y;
                }
                if (edge) {
#pragma unroll
                    for (int nj = 0; nj < 8; nj++)
#pragma unroll
                        for (int e = 0; e < 2; e++)
                            if (colb + nj * 8 + e >= VOCAB) vv[nj][e] = -3.0e38f;
                }
                float tm = -3.0e38f;
#pragma unroll
                for (int nj = 0; nj < 8; nj++) {
                    tm = fmaxf(tm, vv[nj][0]);
                    tm = fmaxf(tm, vv[nj][1]);
                }
                tm = fmaxf(tm, __shfl_xor_sync(0xFFFFFFFFu, tm, 1));
                tm = fmaxf(tm, __shfl_xor_sync(0xFFFFFFFFu, tm, 2));
                float nm = fmaxf(m_run[sl], tm);
                float p = 0.0f;
#pragma unroll
                for (int nj = 0; nj < 8; nj++) {
                    p += __expf(vv[nj][0] - nm);
                    p += __expf(vv[nj][1] - nm);
                }
                p += __shfl_xor_sync(0xFFFFFFFFu, p, 1);
                p += __shfl_xor_sync(0xFFFFFFFFu, p, 2);
                s_run[sl] = s_run[sl] * __expf(m_run[sl] - nm) + p;
                m_run[sl] = nm;
            }
            v0 += 128;
#pragma unroll
            for (int mi = 0; mi < 2; mi++)
#pragma unroll
                for (int nj = 0; nj < 8; nj++) { c[mi][nj][0] = 0u; c[mi][nj][1] = 0u; }
        }
    }

    // ---- store per-row partials keyed by (s, wn) ----
    if ((lane & 3) == 0) {
#pragma unroll
        for (int sl = 0; sl < 4; sl++) {
            const int mi = sl >> 1, h = sl & 1;
            int row = m0 + wm * 32 + mi * 16 + h * 8 + (lane >> 2);
            g_pmax[s][wn][row] = m_run[sl];
            g_psum[s][wn][row] = s_run[sl];
        }
    }
}

// ---------------- kernel 4: label logits from the SAME fp16 operands ----------------
__global__ void label_logit_kernel(const int* __restrict__ label) {
    int wid = threadIdx.x >> 5, lid = threadIdx.x & 31;
    int row = blockIdx.x * 8 + wid;
    int lab = label[row];
    const __half2* xr = reinterpret_cast<const __half2*>(&g_X[(size_t)row * NEMBD]);
    const __half2* wr = reinterpret_cast<const __half2*>(&g_W[(size_t)lab * NEMBD]);
    float acc = 0.f;
#pragma unroll
    for (int it = 0; it < 12; it++) {
        __half2 x2 = xr[it * 32 + lid];
        __half2 w2 = wr[it * 32 + lid];
        acc += __low2float(x2) * __low2float(w2) + __high2float(x2) * __high2float(w2);
    }
#pragma unroll
    for (int o = 16; o; o >>= 1) acc += __shfl_xor_sync(0xFFFFFFFFu, acc, o);
    if (lid == 0) g_ll[row] = acc;
}

// ---------------- kernel 5a: per-row NLL ----------------
__global__ void rownll_kernel() {
    int r = blockIdx.x * 256 + threadIdx.x;
    float m = g_pmax[0][0][r];
#pragma unroll
    for (int s = 0; s < NSPLIT; s++) {
        m = fmaxf(m, g_pmax[s][0][r]);
        m = fmaxf(m, g_pmax[s][1][r]);
    }
    float S = 0.f;
#pragma unroll
    for (int s = 0; s < NSPLIT; s++) {
        S += g_psum[s][0][r] * __expf(g_pmax[s][0][r] - m);
        S += g_psum[s][1][r] * __expf(g_pmax[s][1][r] - m);
    }
    g_row[r] = (m + logf(S)) - g_ll[r];
}

// ---------------- kernel 5b: deterministic mean ----------------
__global__ void reduce_kernel(float* __restrict__ out) {
    __shared__ float red[256];
    int t = threadIdx.x;
    float local = 0.f;
#pragma unroll
    for (int i = 0; i < NROWS / 256; i++) local += g_row[t + i * 256];
    red[t] = local;
    __syncthreads();
    for (int off = 128; off; off >>= 1) {
        if (t < off) red[t] += red[t + off];
        __syncthreads();
    }
    if (t == 0) out[0] = red[0] * (1.0f / (float)NROWS);
}

// ---------------- launch ----------------
extern "C" void kernel_launch(void* const* d_in, const int* in_sizes, int n_in,
                              void* d_out, int out_size) {
    const int*   data  = (const int*)d_in[0];
    const int*   label = (const int*)d_in[1];
    const float* wte   = (const float*)d_in[2];
    const float* wpe   = (const float*)d_in[3];
    const float* W     = (const float*)d_in[4];
    float* out = (float*)d_out;

    cudaFuncSetAttribute(gemm_lse_kernel, cudaFuncAttributeMaxDynamicSharedMemorySize, SMEM_BYTES);

    prep_x_kernel<<<(NROWS * (NEMBD / 4)) / 256, 256>>>(data, wte, wpe);
    conv_w_kernel<<<(VPAD * (NEMBD / 4)) / 256, 256>>>(W);
    gemm_lse_kernel<<<dim3(NSPLIT, NROWS / 128), 256, SMEM_BYTES>>>();
    label_logit_kernel<<<NROWS / 8, 256>>>(label);
    rownll_kernel<<<NROWS / 256, 256>>>();
    reduce_kernel<<<1, 256>>>(out);
}